// round 1
// baseline (speedup 1.0000x reference)
#include <cuda_runtime.h>
#include <math.h>

#define HH 512
#define WW 512
#define AA 180
#define CHUNK 64
#define PREW (WW + 1)      // 513 float2 per padded row
#define PREH (HH + 2)      // 514 padded rows

// Scratch (no allocation allowed in kernel_launch):
__device__ float2 g_pre[PREH * PREW];   // padded pair image: ~2.1 MB
__device__ float  g_sino[AA * WW];      // radon accumulator
__device__ double g_acc[2];             // [0]=sum (proj-sino)^2, [1]=sum tv

// ---------------------------------------------------------------------------
// Kernel 1: build padded float2 pair image, zero accumulators.
// pre[r][c] = ( P(r,c), P(r,c+1) ), P(r,c) = pred[r-1][c-1] inside, else 0.
// ---------------------------------------------------------------------------
__global__ void prep_kernel(const float* __restrict__ pred) {
    int idx = blockIdx.x * blockDim.x + threadIdx.x;
    const int total = PREH * PREW;
    if (idx < total) {
        int r = idx / PREW;
        int c = idx - r * PREW;
        float a = 0.0f, b = 0.0f;
        if (r >= 1 && r <= HH) {
            const float* row = pred + (r - 1) * WW;
            if (c >= 1 && c <= WW) a = row[c - 1];
            if (c <= WW - 1)       b = row[c];      // (c+1) in [1,WW] <=> c in [0,WW-1]
        }
        g_pre[idx] = make_float2(a, b);
    }
    if (idx < AA * WW) g_sino[idx] = 0.0f;
    if (idx < 2)       g_acc[idx]  = 0.0;
}

// ---------------------------------------------------------------------------
// Kernel 2: radon gather. blockIdx.x = angle, blockIdx.y = h-chunk.
// thread w walks h within the chunk: (ix,iy) = base + j*(-sin, cos).
// ---------------------------------------------------------------------------
__global__ __launch_bounds__(WW) void radon_kernel(const float* __restrict__ angles) {
    const int a  = blockIdx.x;
    const int h0 = blockIdx.y * CHUNK;
    const int w  = threadIdx.x;

    const float ang = angles[a];
    const float s  = sinf(ang);
    const float co = cosf(ang);

    const float xw  = (2.0f * (float)w  + 1.0f) / (float)WW - 1.0f;
    const float yh0 = (2.0f * (float)h0 + 1.0f) / (float)HH - 1.0f;

    // ix = ((gx+1)*W - 1)*0.5, gx = cos*xw - sin*yh ; step per h: dix = -sin*W/H
    const float ix0 = ((co * xw - s * yh0 + 1.0f) * (float)WW - 1.0f) * 0.5f;
    const float iy0 = ((s * xw + co * yh0 + 1.0f) * (float)HH - 1.0f) * 0.5f;
    const float dix = -s * ((float)WW / (float)HH);
    const float diy =  co;

    float acc = 0.0f;

    #pragma unroll 4
    for (int j = 0; j < CHUNK; j++) {
        const float jf = (float)j;
        const float ix = fmaf(jf, dix, ix0);
        const float iy = fmaf(jf, diy, iy0);
        const float xf = floorf(ix);
        const float yf = floorf(iy);
        const float wx = ix - xf;
        const float wy = iy - yf;
        const int x0 = (int)xf;
        const int y0 = (int)yf;
        const unsigned cx = (unsigned)(x0 + 1);   // valid iff x0 in [-1, W-1]
        const unsigned cy = (unsigned)(y0 + 1);   // valid iff y0 in [-1, H-1]
        if (cx <= (unsigned)WW && cy <= (unsigned)HH) {
            const int base = (int)cy * PREW + (int)cx;
            const float2 t = g_pre[base];          // (v00, v01)
            const float2 b = g_pre[base + PREW];   // (v10, v11)
            const float top = fmaf(wx, t.y - t.x, t.x);
            const float bot = fmaf(wx, b.y - b.x, b.x);
            acc += fmaf(wy, bot - top, top);
        }
    }
    atomicAdd(&g_sino[a * WW + w], acc);
}

// ---------------------------------------------------------------------------
// Kernel 3: fused MSE + TV reduction.
// ---------------------------------------------------------------------------
__global__ void loss_kernel(const float* __restrict__ pred,
                            const float* __restrict__ sino_tgt) {
    const int tid    = blockIdx.x * blockDim.x + threadIdx.x;
    const int stride = gridDim.x * blockDim.x;

    float lp = 0.0f;
    for (int i = tid; i < AA * WW; i += stride) {
        const float d = g_sino[i] - sino_tgt[i];
        lp = fmaf(d, d, lp);
    }

    float lt = 0.0f;
    const int TVW = WW - 1, TVH = HH - 1;
    for (int i = tid; i < TVH * TVW; i += stride) {
        const int y = i / TVW;
        const int x = i - y * TVW;
        const float p  = pred[y * WW + x];
        const float dx = pred[y * WW + x + 1] - p;
        const float dy = pred[(y + 1) * WW + x] - p;
        lt += sqrtf(fmaf(dx, dx, fmaf(dy, dy, 1e-8f)));
    }

    // warp reduce
    for (int off = 16; off > 0; off >>= 1) {
        lp += __shfl_down_sync(0xFFFFFFFFu, lp, off);
        lt += __shfl_down_sync(0xFFFFFFFFu, lt, off);
    }
    __shared__ float s_lp[32], s_lt[32];
    const int lane = threadIdx.x & 31;
    const int warp = threadIdx.x >> 5;
    if (lane == 0) { s_lp[warp] = lp; s_lt[warp] = lt; }
    __syncthreads();
    const int nwarps = blockDim.x >> 5;
    if (warp == 0) {
        lp = (lane < nwarps) ? s_lp[lane] : 0.0f;
        lt = (lane < nwarps) ? s_lt[lane] : 0.0f;
        for (int off = 16; off > 0; off >>= 1) {
            lp += __shfl_down_sync(0xFFFFFFFFu, lp, off);
            lt += __shfl_down_sync(0xFFFFFFFFu, lt, off);
        }
        if (lane == 0) {
            atomicAdd(&g_acc[0], (double)lp);
            atomicAdd(&g_acc[1], (double)lt);
        }
    }
}

// ---------------------------------------------------------------------------
// Kernel 4: finalize scalar loss.
// ---------------------------------------------------------------------------
__global__ void finalize_kernel(float* __restrict__ out) {
    const double loss_proj = g_acc[0] / (double)(AA * WW);
    const double loss_tv   = g_acc[1] / (double)((HH - 1) * (WW - 1));
    out[0] = (float)(loss_proj + 0.01 * loss_tv);
}

// ---------------------------------------------------------------------------
extern "C" void kernel_launch(void* const* d_in, const int* in_sizes, int n_in,
                              void* d_out, int out_size) {
    const float* pred     = (const float*)d_in[0];   // [1,512,512]
    const float* sinogram = (const float*)d_in[1];   // [1,180,512]
    const float* angles   = (const float*)d_in[2];   // [180]
    float* out = (float*)d_out;

    const int prep_total = PREH * PREW;              // 263,682
    prep_kernel<<<(prep_total + 255) / 256, 256>>>(pred);

    dim3 rgrid(AA, HH / CHUNK);                      // 180 x 8
    radon_kernel<<<rgrid, WW>>>(angles);

    loss_kernel<<<256, 256>>>(pred, sinogram);

    finalize_kernel<<<1, 1>>>(out);
}